// round 4
// baseline (speedup 1.0000x reference)
#include <cuda_runtime.h>

#define S_  16
#define T_  400
#define F_  16
#define SF_ 250
#define G_  4
#define H1  32
#define H2  16

#define OBS_STRIDE 20
#define THREADS    256
#define CHUNKS     27
#define ROWS_S     (T_ * (SF_ + 1))                    // 100400
#define ROWS_CTA   ((ROWS_S + CHUNKS - 1) / CHUNKS)    // 3719

typedef unsigned long long ull;

__device__ __forceinline__ ull pk2(float a, float b) {
    ull r; asm("mov.b64 %0, {%1,%2};" : "=l"(r) : "f"(a), "f"(b)); return r;
}
__device__ __forceinline__ void upk(ull p, float& a, float& b) {
    asm("mov.b64 {%0,%1}, %2;" : "=f"(a), "=f"(b) : "l"(p));
}
__device__ __forceinline__ ull fma2(ull a, ull b, ull c) {
    ull d; asm("fma.rn.f32x2 %0, %1, %2, %3;" : "=l"(d) : "l"(a), "l"(b), "l"(c)); return d;
}
__device__ __forceinline__ float lrelu(float x) { return fmaxf(x, 0.01f * x); }

struct RowIdx { int t0, t1, t2, t3; };

__device__ __forceinline__ RowIdx load_idx(const int* __restrict__ perm, int s, int idx) {
    RowIdx r;
    int sfp = idx / T_;
    int t   = idx - sfp * T_;
    if (sfp == 0) { r.t0 = r.t1 = r.t2 = r.t3 = t; }
    else {
        int base = ((sfp - 1) * (G_ * S_) + s) * T_ + t;
        r.t0 = perm[base];
        r.t1 = perm[base + S_ * T_];
        r.t2 = perm[base + 2 * S_ * T_];
        r.t3 = perm[base + 3 * S_ * T_];
    }
    return r;
}

__global__ __launch_bounds__(THREADS, 3)
void fused_kernel(const float* __restrict__ obs,
                  const float* __restrict__ mu,
                  const float* __restrict__ Sig,
                  const int*   __restrict__ perm,
                  const float* __restrict__ W1,
                  const float* __restrict__ b1,
                  const float* __restrict__ W2,
                  const float* __restrict__ b2,
                  const float* __restrict__ W3,
                  const float* __restrict__ b3,
                  float* __restrict__ out) {
    __shared__ __align__(16) float sObs[T_ * OBS_STRIDE];  // 32000 B
    __shared__ __align__(16) float sW1[F_ * H1];           // W1eff [j][c]
    __shared__ __align__(16) float sW2[H1 * H2];           // [i][j]
    __shared__ __align__(16) float sB1[H1];
    __shared__ __align__(16) float sB2[H2];
    __shared__ __align__(16) float sW3[H2];

    const int s   = blockIdx.y;
    const int k   = blockIdx.x;
    const int tid = threadIdx.x;

    // ---- stage obs slice (padded rows) ----
    const float4* osrc = (const float4*)(obs + s * (T_ * F_));
    for (int m = tid; m < T_ * F_ / 4; m += THREADS) {
        int t = m >> 2, q = m & 3;
        *(float4*)(sObs + t * OBS_STRIDE + q * 4) = osrc[m];
    }
    // ---- W1eff = Sigma^T W1 (normalize folded into layer 1) ----
    for (int m = tid; m < F_ * H1; m += THREADS) {
        int j = m >> 5, c = m & 31;
        float acc = 0.f;
        #pragma unroll
        for (int i = 0; i < F_; i++) acc += Sig[i * F_ + j] * W1[i * H1 + c];
        sW1[j * H1 + c] = acc;
    }
    // ---- b1eff = b1 - mu^T W1eff ----
    if (tid < H1) {
        int c = tid;
        float bacc = 0.f;
        #pragma unroll
        for (int j = 0; j < F_; j++) {
            float wj = 0.f;
            #pragma unroll
            for (int i = 0; i < F_; i++) wj += Sig[i * F_ + j] * W1[i * H1 + c];
            bacc += mu[j] * wj;
        }
        sB1[c] = b1[c] - bacc;
    }
    for (int m = tid; m < H1 * H2; m += THREADS) sW2[m] = W2[m];
    if (tid < H2) sB2[tid] = b2[tid];
    if (tid < H2) sW3[tid] = W3[tid];
    __syncthreads();

    const float b3v = b3[0];
    const int rowsBeg = k * ROWS_CTA;
    const int rowsEnd = (rowsBeg + ROWS_CTA < ROWS_S) ? rowsBeg + ROWS_CTA : ROWS_S;
    float* outS = out + s * ROWS_S;

    int idx = rowsBeg + tid;
    if (idx >= rowsEnd) return;

    RowIdx r = load_idx(perm, s, idx);   // prime pipeline

    while (true) {
        const int cur = idx;
        RowIdx ci = r;

        // prefetch next iteration's perm indices (hides LDG latency)
        idx += THREADS;
        const bool more = (idx < rowsEnd);
        if (more) r = load_idx(perm, s, idx);

        // ---- gather shuffled feature vector (4 x float4) ----
        float x[16];
        *(float4*)(x + 0)  = *(const float4*)(sObs + ci.t0 * OBS_STRIDE + 0);
        *(float4*)(x + 4)  = *(const float4*)(sObs + ci.t1 * OBS_STRIDE + 4);
        *(float4*)(x + 8)  = *(const float4*)(sObs + ci.t2 * OBS_STRIDE + 8);
        *(float4*)(x + 12) = *(const float4*)(sObs + ci.t3 * OBS_STRIDE + 12);

        // ---- layer-2 accumulators (init with b2, c-packed) ----
        ull c2[8];
        {
            const ull* pb = (const ull*)sB2;
            #pragma unroll
            for (int p = 0; p < 8; p++) c2[p] = pb[p];
        }

        // ---- layer 1 in two 16-wide halves, fused with lrelu + layer-2 accum ----
        #pragma unroll
        for (int half = 0; half < 2; half++) {
            ull h[8];
            {
                const ull* pb = (const ull*)(sB1 + half * 16);
                #pragma unroll
                for (int p = 0; p < 8; p++) h[p] = pb[p];
            }
            #pragma unroll
            for (int j = 0; j < F_; j++) {
                ull xj = pk2(x[j], x[j]);
                const ulonglong2* w = (const ulonglong2*)(sW1 + j * H1 + half * 16);
                #pragma unroll
                for (int q = 0; q < 4; q++) {
                    ulonglong2 ww = w[q];
                    h[2 * q]     = fma2(xj, ww.x, h[2 * q]);
                    h[2 * q + 1] = fma2(xj, ww.y, h[2 * q + 1]);
                }
            }
            // lrelu + accumulate into layer-2 partials
            #pragma unroll
            for (int p = 0; p < 8; p++) {
                float u, v;
                upk(h[p], u, v);
                float au = lrelu(u), av = lrelu(v);
                ull au2 = pk2(au, au), av2 = pk2(av, av);
                int i0 = half * 16 + 2 * p;
                const ulonglong2* w0 = (const ulonglong2*)(sW2 + i0 * H2);
                const ulonglong2* w1 = (const ulonglong2*)(sW2 + (i0 + 1) * H2);
                #pragma unroll
                for (int q = 0; q < 4; q++) {
                    ulonglong2 wu = w0[q];
                    ulonglong2 wv = w1[q];
                    c2[2 * q]     = fma2(au2, wu.x, c2[2 * q]);
                    c2[2 * q + 1] = fma2(au2, wu.y, c2[2 * q + 1]);
                    c2[2 * q]     = fma2(av2, wv.x, c2[2 * q]);
                    c2[2 * q + 1] = fma2(av2, wv.y, c2[2 * q + 1]);
                }
            }
        }

        // ---- layer 3 + sigmoid ----
        float z = b3v;
        #pragma unroll
        for (int p = 0; p < 8; p++) {
            float u, v;
            upk(c2[p], u, v);
            z += lrelu(u) * sW3[2 * p] + lrelu(v) * sW3[2 * p + 1];
        }
        outS[cur] = 1.f / (1.f + __expf(-z));

        if (!more) break;
    }
}

extern "C" void kernel_launch(void* const* d_in, const int* in_sizes, int n_in,
                              void* d_out, int out_size) {
    const float* obs  = (const float*)d_in[0];
    const float* mu   = (const float*)d_in[1];
    const float* Sig  = (const float*)d_in[2];
    const int*   perm = (const int*)d_in[3];
    const float* W1   = (const float*)d_in[4];
    const float* b1   = (const float*)d_in[5];
    const float* W2   = (const float*)d_in[6];
    const float* b2   = (const float*)d_in[7];
    const float* W3   = (const float*)d_in[8];
    const float* b3   = (const float*)d_in[9];
    float* out = (float*)d_out;

    dim3 grid(CHUNKS, S_);
    fused_kernel<<<grid, THREADS>>>(obs, mu, Sig, perm, W1, b1, W2, b2, W3, b3, out);
}

// round 5
// speedup vs baseline: 1.4157x; 1.4157x over previous
#include <cuda_runtime.h>

#define S_  16
#define T_  400
#define F_  16
#define SF_ 250
#define G_  4
#define H1  32
#define H2  16

#define OBS_STRIDE 20
#define THREADS    512
#define CHUNKS     9
#define ROWS_S     (T_ * (SF_ + 1))                    // 100400
#define ROWS_CTA   ((ROWS_S + CHUNKS - 1) / CHUNKS)    // 11156

typedef unsigned long long ull;

__device__ __forceinline__ ull pk2(float a, float b) {
    ull r; asm("mov.b64 %0, {%1,%2};" : "=l"(r) : "f"(a), "f"(b)); return r;
}
__device__ __forceinline__ void upk(ull p, float& a, float& b) {
    asm("mov.b64 {%0,%1}, %2;" : "=f"(a), "=f"(b) : "l"(p));
}
__device__ __forceinline__ ull fma2(ull a, ull b, ull c) {
    ull d; asm("fma.rn.f32x2 %0, %1, %2, %3;" : "=l"(d) : "l"(a), "l"(b), "l"(c)); return d;
}
__device__ __forceinline__ float lrelu(float x) { return fmaxf(x, 0.01f * x); }

struct RowIdx { int t0, t1, t2, t3; };

__device__ __forceinline__ RowIdx load_idx(const int* __restrict__ perm, int s, int idx) {
    RowIdx r;
    int sfp = idx / T_;
    int t   = idx - sfp * T_;
    if (sfp == 0) { r.t0 = r.t1 = r.t2 = r.t3 = t; }
    else {
        int base = ((sfp - 1) * (G_ * S_) + s) * T_ + t;
        r.t0 = perm[base];
        r.t1 = perm[base + S_ * T_];
        r.t2 = perm[base + 2 * S_ * T_];
        r.t3 = perm[base + 3 * S_ * T_];
    }
    return r;
}

__global__ __launch_bounds__(THREADS, 1)
void fused_kernel(const float* __restrict__ obs,
                  const float* __restrict__ mu,
                  const float* __restrict__ Sig,
                  const int*   __restrict__ perm,
                  const float* __restrict__ W1,
                  const float* __restrict__ b1,
                  const float* __restrict__ W2,
                  const float* __restrict__ b2,
                  const float* __restrict__ W3,
                  const float* __restrict__ b3,
                  float* __restrict__ out) {
    __shared__ __align__(16) float sObs[T_ * OBS_STRIDE];  // 32000 B
    __shared__ __align__(16) float sW1[F_ * H1];           // W1eff [j][c]
    __shared__ __align__(16) float sW2[H1 * H2];           // [i][j]
    __shared__ __align__(16) float sB1[H1];
    __shared__ __align__(16) float sB2[H2];
    __shared__ __align__(16) float sW3[H2];

    const int s   = blockIdx.y;
    const int k   = blockIdx.x;
    const int tid = threadIdx.x;

    // ---- stage obs slice (padded rows) ----
    const float4* osrc = (const float4*)(obs + s * (T_ * F_));
    for (int m = tid; m < T_ * F_ / 4; m += THREADS) {
        int t = m >> 2, q = m & 3;
        *(float4*)(sObs + t * OBS_STRIDE + q * 4) = osrc[m];
    }
    // ---- W1eff = Sigma^T W1 (normalize folded into layer 1) ----
    for (int m = tid; m < F_ * H1; m += THREADS) {
        int j = m >> 5, c = m & 31;
        float acc = 0.f;
        #pragma unroll
        for (int i = 0; i < F_; i++) acc += Sig[i * F_ + j] * W1[i * H1 + c];
        sW1[j * H1 + c] = acc;
    }
    // ---- b1eff = b1 - mu^T W1eff ----
    if (tid < H1) {
        int c = tid;
        float bacc = 0.f;
        #pragma unroll
        for (int j = 0; j < F_; j++) {
            float wj = 0.f;
            #pragma unroll
            for (int i = 0; i < F_; i++) wj += Sig[i * F_ + j] * W1[i * H1 + c];
            bacc += mu[j] * wj;
        }
        sB1[c] = b1[c] - bacc;
    }
    for (int m = tid; m < H1 * H2; m += THREADS) sW2[m] = W2[m];
    if (tid < H2) sB2[tid] = b2[tid];
    if (tid < H2) sW3[tid] = W3[tid];
    __syncthreads();

    const float b3v = b3[0];
    const int rowsBeg = k * ROWS_CTA;
    const int rowsEnd = (rowsBeg + ROWS_CTA < ROWS_S) ? rowsBeg + ROWS_CTA : ROWS_S;
    float* outS = out + s * ROWS_S;

    const int stride = 2 * THREADS;
    int idxA = rowsBeg + tid;
    if (idxA >= rowsEnd) return;

    int idxB = idxA + THREADS;
    bool hasB = (idxB < rowsEnd);
    RowIdx ra = load_idx(perm, s, idxA);
    RowIdx rb = load_idx(perm, s, hasB ? idxB : idxA);

    while (true) {
        const int curA = idxA, curB = hasB ? idxB : idxA;
        const bool curHasB = hasB;
        RowIdx ca = ra, cb = rb;

        // ---- prefetch next iteration's perm indices ----
        idxA += stride;
        const bool more = (idxA < rowsEnd);
        if (more) {
            idxB = idxA + THREADS;
            hasB = (idxB < rowsEnd);
            ra = load_idx(perm, s, idxA);
            rb = load_idx(perm, s, hasB ? idxB : idxA);
        }

        // ---- gather shuffled feature vectors ----
        float xA[16], xB[16];
        *(float4*)(xA + 0)  = *(const float4*)(sObs + ca.t0 * OBS_STRIDE + 0);
        *(float4*)(xA + 4)  = *(const float4*)(sObs + ca.t1 * OBS_STRIDE + 4);
        *(float4*)(xA + 8)  = *(const float4*)(sObs + ca.t2 * OBS_STRIDE + 8);
        *(float4*)(xA + 12) = *(const float4*)(sObs + ca.t3 * OBS_STRIDE + 12);
        *(float4*)(xB + 0)  = *(const float4*)(sObs + cb.t0 * OBS_STRIDE + 0);
        *(float4*)(xB + 4)  = *(const float4*)(sObs + cb.t1 * OBS_STRIDE + 4);
        *(float4*)(xB + 8)  = *(const float4*)(sObs + cb.t2 * OBS_STRIDE + 8);
        *(float4*)(xB + 12) = *(const float4*)(sObs + cb.t3 * OBS_STRIDE + 12);

        // ---- layer-2 accumulators (init with b2) ----
        ull cA2[8], cB2[8];
        {
            const ull* pb = (const ull*)sB2;
            #pragma unroll
            for (int p = 0; p < 8; p++) { cA2[p] = pb[p]; cB2[p] = pb[p]; }
        }

        // ---- layer 1 in two 16-wide halves, fused lrelu + layer-2 accum ----
        #pragma unroll
        for (int half = 0; half < 2; half++) {
            ull hA[8], hB[8];
            {
                const ull* pb = (const ull*)(sB1 + half * 16);
                #pragma unroll
                for (int p = 0; p < 8; p++) { hA[p] = pb[p]; hB[p] = pb[p]; }
            }
            #pragma unroll
            for (int j = 0; j < F_; j++) {
                ull aj = pk2(xA[j], xA[j]);
                ull bj = pk2(xB[j], xB[j]);
                const ulonglong2* w = (const ulonglong2*)(sW1 + j * H1 + half * 16);
                #pragma unroll
                for (int q = 0; q < 4; q++) {
                    ulonglong2 ww = w[q];
                    hA[2 * q]     = fma2(aj, ww.x, hA[2 * q]);
                    hA[2 * q + 1] = fma2(aj, ww.y, hA[2 * q + 1]);
                    hB[2 * q]     = fma2(bj, ww.x, hB[2 * q]);
                    hB[2 * q + 1] = fma2(bj, ww.y, hB[2 * q + 1]);
                }
            }
            #pragma unroll
            for (int p = 0; p < 8; p++) {
                float u, v;
                upk(hA[p], u, v);
                float au = lrelu(u), av = lrelu(v);
                upk(hB[p], u, v);
                float bu = lrelu(u), bv = lrelu(v);
                ull au2 = pk2(au, au), av2 = pk2(av, av);
                ull bu2 = pk2(bu, bu), bv2 = pk2(bv, bv);
                int i0 = half * 16 + 2 * p;
                const ulonglong2* w0 = (const ulonglong2*)(sW2 + i0 * H2);
                const ulonglong2* w1 = (const ulonglong2*)(sW2 + (i0 + 1) * H2);
                #pragma unroll
                for (int q = 0; q < 4; q++) {
                    ulonglong2 wu = w0[q];
                    ulonglong2 wv = w1[q];
                    cA2[2 * q]     = fma2(au2, wu.x, cA2[2 * q]);
                    cA2[2 * q + 1] = fma2(au2, wu.y, cA2[2 * q + 1]);
                    cB2[2 * q]     = fma2(bu2, wu.x, cB2[2 * q]);
                    cB2[2 * q + 1] = fma2(bu2, wu.y, cB2[2 * q + 1]);
                    cA2[2 * q]     = fma2(av2, wv.x, cA2[2 * q]);
                    cA2[2 * q + 1] = fma2(av2, wv.y, cA2[2 * q + 1]);
                    cB2[2 * q]     = fma2(bv2, wv.x, cB2[2 * q]);
                    cB2[2 * q + 1] = fma2(bv2, wv.y, cB2[2 * q + 1]);
                }
            }
        }

        // ---- layer 3 + sigmoid ----
        float zA = b3v, zB = b3v;
        #pragma unroll
        for (int p = 0; p < 8; p++) {
            float u, v;
            upk(cA2[p], u, v); zA += lrelu(u) * sW3[2 * p] + lrelu(v) * sW3[2 * p + 1];
            upk(cB2[p], u, v); zB += lrelu(u) * sW3[2 * p] + lrelu(v) * sW3[2 * p + 1];
        }
        outS[curA] = 1.f / (1.f + __expf(-zA));
        if (curHasB) outS[curB] = 1.f / (1.f + __expf(-zB));

        if (!more) break;
    }
}

extern "C" void kernel_launch(void* const* d_in, const int* in_sizes, int n_in,
                              void* d_out, int out_size) {
    const float* obs  = (const float*)d_in[0];
    const float* mu   = (const float*)d_in[1];
    const float* Sig  = (const float*)d_in[2];
    const int*   perm = (const int*)d_in[3];
    const float* W1   = (const float*)d_in[4];
    const float* b1   = (const float*)d_in[5];
    const float* W2   = (const float*)d_in[6];
    const float* b2   = (const float*)d_in[7];
    const float* W3   = (const float*)d_in[8];
    const float* b3   = (const float*)d_in[9];
    float* out = (float*)d_out;

    dim3 grid(CHUNKS, S_);
    fused_kernel<<<grid, THREADS>>>(obs, mu, Sig, perm, W1, b1, W2, b2, W3, b3, out);
}